// round 1
// baseline (speedup 1.0000x reference)
#include <cuda_runtime.h>

#define EPS_DEN 1e-9f
#define EPS_IN  1e-6f

__global__ void iou_zero_kernel(float* out) {
    if (threadIdx.x == 0 && blockIdx.x == 0) out[0] = 0.0f;
}

__global__ __launch_bounds__(256)
void iou_loss_kernel(const float* __restrict__ gt,
                     const float* __restrict__ det,
                     const int*   __restrict__ sizes,
                     float* __restrict__ out,
                     int B, int N)
{
    int idx   = blockIdx.x * blockDim.x + threadIdx.x;
    int total = B * N;
    float loss = 0.0f;

    if (idx < total) {
        int b = idx / N;
        // wh = [sizes[:,1], sizes[:,0]] -> x scaled by width, y by height
        float sx = (float)sizes[2 * b + 1];
        float sy = (float)sizes[2 * b + 0];

        const float* g  = gt  + (size_t)idx * 8;
        const float* dd = det + (size_t)idx * 8;

        float p1x[4], p1y[4], p2x[4], p2y[4];
        #pragma unroll
        for (int k = 0; k < 4; k++) {
            p1x[k] = g[2 * k]     * sx;
            p1y[k] = g[2 * k + 1] * sy;
            p2x[k] = dd[2 * k];
            p2y[k] = dd[2 * k + 1];
        }

        float ptx[24], pty[24];
        bool  msk[24];

        // ---- 16 edge-pair intersections (i = p1 edge major, j = p2 edge minor,
        //      matching the reference reshape order) ----
        #pragma unroll
        for (int i = 0; i < 4; i++) {
            int i1 = (i + 1) & 3;
            float a0x = p1x[i], a0y = p1y[i];
            float d1x = p1x[i1] - a0x, d1y = p1y[i1] - a0y;
            #pragma unroll
            for (int j = 0; j < 4; j++) {
                int j1 = (j + 1) & 3;
                float b0x = p2x[j], b0y = p2y[j];
                float d2x = p2x[j1] - b0x, d2y = p2y[j1] - b0y;
                float rx = b0x - a0x, ry = b0y - a0y;
                float den = d1x * d2y - d1y * d2x;
                bool  dok = fabsf(den) > EPS_DEN;
                float safe = dok ? den : 1.0f;
                float t = (rx * d2y - ry * d2x) / safe;
                float u = (rx * d1y - ry * d1x) / safe;
                bool v = dok && (t >= 0.0f) && (t <= 1.0f)
                             && (u >= 0.0f) && (u <= 1.0f);
                int kk = i * 4 + j;
                ptx[kk] = a0x + t * d1x;
                pty[kk] = a0y + t * d1y;
                msk[kk] = v;
            }
        }

        // ---- p1 vertices inside p2 ----
        #pragma unroll
        for (int q = 0; q < 4; q++) {
            bool allpos = true, allneg = true;
            #pragma unroll
            for (int e = 0; e < 4; e++) {
                int e1 = (e + 1) & 3;
                float ex = p2x[e1] - p2x[e], ey = p2y[e1] - p2y[e];
                float dx = p1x[q] - p2x[e], dy = p1y[q] - p2y[e];
                float cr = ex * dy - ey * dx;
                allpos = allpos && (cr >= -EPS_IN);
                allneg = allneg && (cr <=  EPS_IN);
            }
            ptx[16 + q] = p1x[q];
            pty[16 + q] = p1y[q];
            msk[16 + q] = allpos || allneg;
        }

        // ---- p2 vertices inside p1 ----
        #pragma unroll
        for (int q = 0; q < 4; q++) {
            bool allpos = true, allneg = true;
            #pragma unroll
            for (int e = 0; e < 4; e++) {
                int e1 = (e + 1) & 3;
                float ex = p1x[e1] - p1x[e], ey = p1y[e1] - p1y[e];
                float dx = p2x[q] - p1x[e], dy = p2y[q] - p1y[e];
                float cr = ex * dy - ey * dx;
                allpos = allpos && (cr >= -EPS_IN);
                allneg = allneg && (cr <=  EPS_IN);
            }
            ptx[20 + q] = p2x[q];
            pty[20 + q] = p2y[q];
            msk[20 + q] = allpos || allneg;
        }

        // ---- centroid of valid points ----
        int cnt = 0;
        float cx = 0.0f, cy = 0.0f;
        #pragma unroll
        for (int k = 0; k < 24; k++) {
            if (msk[k]) { cnt++; cx += ptx[k]; cy += pty[k]; }
        }
        float inv = 1.0f / (float)(cnt > 1 ? cnt : 1);
        cx *= inv;
        cy *= inv;

        // ---- angles (masked-out -> 1e9 so they sort last) ----
        float ang[24];
        #pragma unroll
        for (int k = 0; k < 24; k++) {
            ang[k] = msk[k] ? atan2f(pty[k] - cy, ptx[k] - cx) : 1e9f;
        }

        // ---- stable insertion sort of indices by angle (matches jnp.argsort) ----
        int ord[24];
        for (int k = 0; k < 24; k++) ord[k] = k;
        for (int k = 1; k < 24; k++) {
            int   o = ord[k];
            float a = ang[o];
            int   m = k - 1;
            while (m >= 0 && ang[ord[m]] > a) {
                ord[m + 1] = ord[m];
                m--;
            }
            ord[m + 1] = o;
        }

        // ---- shoelace over sorted points; invalid slots replaced by first ----
        int   o0 = ord[0];
        float fx = ptx[o0], fy = pty[o0];
        float prevx = fx, prevy = fy;
        float s = 0.0f;
        for (int k = 1; k < 24; k++) {
            int o = ord[k];
            float qx = msk[o] ? ptx[o] : fx;
            float qy = msk[o] ? pty[o] : fy;
            s += prevx * qy - qx * prevy;
            prevx = qx;
            prevy = qy;
        }
        s += prevx * fy - fx * prevy;
        float inter = 0.5f * fabsf(s);
        if (cnt < 3) inter = 0.0f;

        // ---- quad areas ----
        float a1 = 0.0f, a2 = 0.0f;
        #pragma unroll
        for (int k = 0; k < 4; k++) {
            int k1 = (k + 1) & 3;
            a1 += p1x[k] * p1y[k1] - p1x[k1] * p1y[k];
            a2 += p2x[k] * p2y[k1] - p2x[k1] * p2y[k];
        }
        a1 = 0.5f * fabsf(a1);
        a2 = 0.5f * fabsf(a2);

        float iou = inter / (a1 + a2 - inter + EPS_DEN);
        loss = 1.0f - iou;
    }

    // ---- block reduction: warp shuffle tree + shared, one atomic per block ----
    __shared__ float sdata[8];
    #pragma unroll
    for (int off = 16; off > 0; off >>= 1)
        loss += __shfl_down_sync(0xffffffff, loss, off);
    int lane = threadIdx.x & 31;
    int wid  = threadIdx.x >> 5;
    if (lane == 0) sdata[wid] = loss;
    __syncthreads();
    if (wid == 0) {
        loss = (lane < (int)(blockDim.x >> 5)) ? sdata[lane] : 0.0f;
        #pragma unroll
        for (int off = 16; off > 0; off >>= 1)
            loss += __shfl_down_sync(0xffffffff, loss, off);
        if (lane == 0) atomicAdd(out, loss / (float)total);
    }
}

extern "C" void kernel_launch(void* const* d_in, const int* in_sizes, int n_in,
                              void* d_out, int out_size)
{
    const float* gt    = (const float*)d_in[0];
    const float* det   = (const float*)d_in[1];
    const int*   sizes = (const int*)d_in[2];
    float*       out   = (float*)d_out;

    int B = in_sizes[2] / 2;              // sizes is (B, 2)
    int N = in_sizes[0] / (8 * B);        // gt_boxes is (B, N, 8)
    int total = B * N;

    iou_zero_kernel<<<1, 32>>>(out);
    int threads = 256;
    int blocks  = (total + threads - 1) / threads;
    iou_loss_kernel<<<blocks, threads>>>(gt, det, sizes, out, B, N);
}

// round 4
// speedup vs baseline: 3.2361x; 3.2361x over previous
#include <cuda_runtime.h>

#define EPS_DEN 1e-9f
#define EPS_IN  1e-6f

__global__ void iou_zero_kernel(float* out) {
    if (threadIdx.x == 0 && blockIdx.x == 0) out[0] = 0.0f;
}

__global__ __launch_bounds__(256)
void iou_loss_kernel(const float4* __restrict__ gt,
                     const float4* __restrict__ det,
                     const int*   __restrict__ sizes,
                     float* __restrict__ out,
                     int B, int N)
{
    int idx   = blockIdx.x * blockDim.x + threadIdx.x;
    int total = B * N;
    float loss = 0.0f;

    if (idx < total) {
        int b = idx / N;
        float sx = (float)sizes[2 * b + 1];
        float sy = (float)sizes[2 * b + 0];

        // each quad = 8 floats = 2 float4
        float4 g0 = gt[2 * idx], g1 = gt[2 * idx + 1];
        float4 d0 = det[2 * idx], d1 = det[2 * idx + 1];

        float p1x[4], p1y[4], p2x[4], p2y[4];
        p1x[0] = g0.x * sx; p1y[0] = g0.y * sy;
        p1x[1] = g0.z * sx; p1y[1] = g0.w * sy;
        p1x[2] = g1.x * sx; p1y[2] = g1.y * sy;
        p1x[3] = g1.z * sx; p1y[3] = g1.w * sy;
        p2x[0] = d0.x; p2y[0] = d0.y;
        p2x[1] = d0.z; p2y[1] = d0.w;
        p2x[2] = d1.x; p2y[2] = d1.y;
        p2x[3] = d1.z; p2y[3] = d1.w;

        float ptx[24], pty[24];
        bool  msk[24];

        // ---- 16 edge-pair intersections ----
        #pragma unroll
        for (int i = 0; i < 4; i++) {
            int i1 = (i + 1) & 3;
            float a0x = p1x[i], a0y = p1y[i];
            float d1x = p1x[i1] - a0x, d1y = p1y[i1] - a0y;
            #pragma unroll
            for (int j = 0; j < 4; j++) {
                int j1 = (j + 1) & 3;
                float b0x = p2x[j], b0y = p2y[j];
                float d2x = p2x[j1] - b0x, d2y = p2y[j1] - b0y;
                float rx = b0x - a0x, ry = b0y - a0y;
                float den = d1x * d2y - d1y * d2x;
                bool  dok = fabsf(den) > EPS_DEN;
                float safe = dok ? den : 1.0f;
                float invd = 1.0f / safe;
                float t = (rx * d2y - ry * d2x) * invd;
                float u = (rx * d1y - ry * d1x) * invd;
                bool v = dok && (t >= 0.0f) && (t <= 1.0f)
                             && (u >= 0.0f) && (u <= 1.0f);
                int kk = i * 4 + j;
                ptx[kk] = a0x + t * d1x;
                pty[kk] = a0y + t * d1y;
                msk[kk] = v;
            }
        }

        // ---- p1 vertices inside p2 ----
        #pragma unroll
        for (int q = 0; q < 4; q++) {
            bool allpos = true, allneg = true;
            #pragma unroll
            for (int e = 0; e < 4; e++) {
                int e1 = (e + 1) & 3;
                float ex = p2x[e1] - p2x[e], ey = p2y[e1] - p2y[e];
                float dx = p1x[q] - p2x[e], dy = p1y[q] - p2y[e];
                float cr = ex * dy - ey * dx;
                allpos = allpos && (cr >= -EPS_IN);
                allneg = allneg && (cr <=  EPS_IN);
            }
            ptx[16 + q] = p1x[q];
            pty[16 + q] = p1y[q];
            msk[16 + q] = allpos || allneg;
        }

        // ---- p2 vertices inside p1 ----
        #pragma unroll
        for (int q = 0; q < 4; q++) {
            bool allpos = true, allneg = true;
            #pragma unroll
            for (int e = 0; e < 4; e++) {
                int e1 = (e + 1) & 3;
                float ex = p1x[e1] - p1x[e], ey = p1y[e1] - p1y[e];
                float dx = p2x[q] - p1x[e], dy = p2y[q] - p1y[e];
                float cr = ex * dy - ey * dx;
                allpos = allpos && (cr >= -EPS_IN);
                allneg = allneg && (cr <=  EPS_IN);
            }
            ptx[20 + q] = p2x[q];
            pty[20 + q] = p2y[q];
            msk[20 + q] = allpos || allneg;
        }

        // ---- quad areas (p1/p2 die after this) ----
        float a1 = 0.0f, a2 = 0.0f;
        #pragma unroll
        for (int k = 0; k < 4; k++) {
            int k1 = (k + 1) & 3;
            a1 += p1x[k] * p1y[k1] - p1x[k1] * p1y[k];
            a2 += p2x[k] * p2y[k1] - p2x[k1] * p2y[k];
        }
        a1 = 0.5f * fabsf(a1);
        a2 = 0.5f * fabsf(a2);

        // ---- centroid of valid points ----
        int cnt = 0;
        float cx = 0.0f, cy = 0.0f;
        #pragma unroll
        for (int k = 0; k < 24; k++) {
            if (msk[k]) { cnt++; cx += ptx[k]; cy += pty[k]; }
        }
        float inv = 1.0f / (float)(cnt > 1 ? cnt : 1);
        cx *= inv;
        cy *= inv;

        // ---- pseudo-angle: monotone equivalent of atan2 over (-pi, pi] ----
        float ang[24];
        #pragma unroll
        for (int k = 0; k < 24; k++) {
            float dx = ptx[k] - cx, dy = pty[k] - cy;
            float r = __fdividef(dx, fabsf(dx) + fabsf(dy) + 1e-30f);
            float p = (dy >= 0.0f) ? (1.0f - r) : (r - 1.0f);
            ang[k] = msk[k] ? p : 1e9f;
        }

        // ---- stable branch-free rank sort ----
        int rk[24];
        #pragma unroll
        for (int k = 0; k < 24; k++) rk[k] = 0;
        #pragma unroll
        for (int a = 0; a < 24; a++) {
            #pragma unroll
            for (int c = a + 1; c < 24; c++) {
                bool le = ang[a] <= ang[c];   // tie -> earlier index first (stable)
                rk[c] += le ? 1 : 0;
                rk[a] += le ? 0 : 1;
            }
        }

        // ---- scatter into sorted order ----
        float sxx[24], syy[24];
        #pragma unroll
        for (int k = 0; k < 24; k++) {
            sxx[rk[k]] = ptx[k];
            syy[rk[k]] = pty[k];
        }

        // ---- shoelace: masked slots (i >= cnt) act as the first point ----
        float s0x = sxx[0], s0y = syy[0];
        float prevx = s0x, prevy = s0y;
        float s = 0.0f;
        #pragma unroll
        for (int i = 1; i < 24; i++) {
            bool v = i < cnt;
            float qx = v ? sxx[i] : s0x;
            float qy = v ? syy[i] : s0y;
            s += prevx * qy - qx * prevy;
            prevx = qx;
            prevy = qy;
        }
        s += prevx * s0y - s0x * prevy;
        float inter = 0.5f * fabsf(s);
        if (cnt < 3) inter = 0.0f;

        float iou = inter / (a1 + a2 - inter + EPS_DEN);
        loss = 1.0f - iou;
    }

    // ---- block reduction ----
    __shared__ float sdata[8];
    #pragma unroll
    for (int off = 16; off > 0; off >>= 1)
        loss += __shfl_down_sync(0xffffffff, loss, off);
    int lane = threadIdx.x & 31;
    int wid  = threadIdx.x >> 5;
    if (lane == 0) sdata[wid] = loss;
    __syncthreads();
    if (wid == 0) {
        loss = (lane < (int)(blockDim.x >> 5)) ? sdata[lane] : 0.0f;
        #pragma unroll
        for (int off = 16; off > 0; off >>= 1)
            loss += __shfl_down_sync(0xffffffff, loss, off);
        if (lane == 0) atomicAdd(out, loss / (float)total);
    }
}

extern "C" void kernel_launch(void* const* d_in, const int* in_sizes, int n_in,
                              void* d_out, int out_size)
{
    const float4* gt    = (const float4*)d_in[0];
    const float4* det   = (const float4*)d_in[1];
    const int*    sizes = (const int*)d_in[2];
    float*        out   = (float*)d_out;

    int B = in_sizes[2] / 2;
    int N = in_sizes[0] / (8 * B);
    int total = B * N;

    iou_zero_kernel<<<1, 32>>>(out);
    int threads = 256;
    int blocks  = (total + threads - 1) / threads;
    iou_loss_kernel<<<blocks, threads>>>(gt, det, sizes, out, B, N);
}

// round 5
// speedup vs baseline: 5.1426x; 1.5891x over previous
#include <cuda_runtime.h>

#define EPS_DEN 1e-9f
#define EPS_IN  1e-6f
#define TPB 128

__global__ void iou_zero_kernel(float* out) {
    if (threadIdx.x == 0 && blockIdx.x == 0) out[0] = 0.0f;
}

__device__ __forceinline__ void ce(unsigned &a, unsigned &b) {
    unsigned lo = min(a, b);
    unsigned hi = max(a, b);
    a = lo; b = hi;
}

__global__ __launch_bounds__(TPB)
void iou_loss_kernel(const float4* __restrict__ gt,
                     const float4* __restrict__ det,
                     const int*   __restrict__ sizes,
                     float* __restrict__ out,
                     int B, int N)
{
    // [slot][tid] layout: bank = tid%32 for any slot -> conflict-free
    __shared__ float px_sh[24][TPB];
    __shared__ float py_sh[24][TPB];
    __shared__ float sdata[TPB / 32];

    int tid   = threadIdx.x;
    int idx   = blockIdx.x * TPB + tid;
    int total = B * N;
    float loss = 0.0f;

    if (idx < total) {
        int b = idx / N;
        float sx = (float)sizes[2 * b + 1];
        float sy = (float)sizes[2 * b + 0];

        float4 g0 = gt[2 * idx],  g1 = gt[2 * idx + 1];
        float4 d0 = det[2 * idx], d1 = det[2 * idx + 1];

        float p1x[4], p1y[4], p2x[4], p2y[4];
        p1x[0] = g0.x * sx; p1y[0] = g0.y * sy;
        p1x[1] = g0.z * sx; p1y[1] = g0.w * sy;
        p1x[2] = g1.x * sx; p1y[2] = g1.y * sy;
        p1x[3] = g1.z * sx; p1y[3] = g1.w * sy;
        p2x[0] = d0.x; p2y[0] = d0.y;
        p2x[1] = d0.z; p2y[1] = d0.w;
        p2x[2] = d1.x; p2y[2] = d1.y;
        p2x[3] = d1.z; p2y[3] = d1.w;

        int   cnt = 0;
        float cx = 0.0f, cy = 0.0f;
        unsigned mbits = 0;

        // ---- 16 edge-pair intersections -> smem slots 0..15 ----
        #pragma unroll
        for (int i = 0; i < 4; i++) {
            int i1 = (i + 1) & 3;
            float a0x = p1x[i], a0y = p1y[i];
            float d1x = p1x[i1] - a0x, d1y = p1y[i1] - a0y;
            #pragma unroll
            for (int j = 0; j < 4; j++) {
                int j1 = (j + 1) & 3;
                float b0x = p2x[j], b0y = p2y[j];
                float d2x = p2x[j1] - b0x, d2y = p2y[j1] - b0y;
                float rx = b0x - a0x, ry = b0y - a0y;
                float den = d1x * d2y - d1y * d2x;
                bool  dok = fabsf(den) > EPS_DEN;
                float invd = 1.0f / (dok ? den : 1.0f);
                float t = (rx * d2y - ry * d2x) * invd;
                float u = (rx * d1y - ry * d1x) * invd;
                bool v = dok && (t >= 0.0f) && (t <= 1.0f)
                             && (u >= 0.0f) && (u <= 1.0f);
                float X = a0x + t * d1x;
                float Y = a0y + t * d1y;
                int kk = i * 4 + j;
                px_sh[kk][tid] = X;
                py_sh[kk][tid] = Y;
                if (v) { mbits |= 1u << kk; cnt++; cx += X; cy += Y; }
            }
        }

        // ---- p1 vertices inside p2 -> slots 16..19 ----
        #pragma unroll
        for (int q = 0; q < 4; q++) {
            bool allpos = true, allneg = true;
            #pragma unroll
            for (int e = 0; e < 4; e++) {
                int e1 = (e + 1) & 3;
                float ex = p2x[e1] - p2x[e], ey = p2y[e1] - p2y[e];
                float dx = p1x[q] - p2x[e], dy = p1y[q] - p2y[e];
                float cr = ex * dy - ey * dx;
                allpos = allpos && (cr >= -EPS_IN);
                allneg = allneg && (cr <=  EPS_IN);
            }
            bool v = allpos || allneg;
            px_sh[16 + q][tid] = p1x[q];
            py_sh[16 + q][tid] = p1y[q];
            if (v) { mbits |= 1u << (16 + q); cnt++; cx += p1x[q]; cy += p1y[q]; }
        }

        // ---- p2 vertices inside p1 -> slots 20..23 ----
        #pragma unroll
        for (int q = 0; q < 4; q++) {
            bool allpos = true, allneg = true;
            #pragma unroll
            for (int e = 0; e < 4; e++) {
                int e1 = (e + 1) & 3;
                float ex = p1x[e1] - p1x[e], ey = p1y[e1] - p1y[e];
                float dx = p2x[q] - p1x[e], dy = p2y[q] - p1y[e];
                float cr = ex * dy - ey * dx;
                allpos = allpos && (cr >= -EPS_IN);
                allneg = allneg && (cr <=  EPS_IN);
            }
            bool v = allpos || allneg;
            px_sh[20 + q][tid] = p2x[q];
            py_sh[20 + q][tid] = p2y[q];
            if (v) { mbits |= 1u << (20 + q); cnt++; cx += p2x[q]; cy += p2y[q]; }
        }

        // ---- quad areas ----
        float a1 = 0.0f, a2 = 0.0f;
        #pragma unroll
        for (int k = 0; k < 4; k++) {
            int k1 = (k + 1) & 3;
            a1 += p1x[k] * p1y[k1] - p1x[k1] * p1y[k];
            a2 += p2x[k] * p2y[k1] - p2x[k1] * p2y[k];
        }
        a1 = 0.5f * fabsf(a1);
        a2 = 0.5f * fabsf(a2);

        // ---- centroid ----
        float inv = 1.0f / (float)(cnt > 1 ? cnt : 1);
        cx *= inv;
        cy *= inv;

        // ---- sortable keys: pseudo-angle uint, index packed in low 5 bits ----
        unsigned key[24];
        #pragma unroll
        for (int k = 0; k < 24; k++) {
            float x = px_sh[k][tid], y = py_sh[k][tid];
            float dx = x - cx, dy = y - cy;
            float r = __fdividef(dx, fabsf(dx) + fabsf(dy) + 1e-30f);
            float p = (dy >= 0.0f) ? (1.0f - r) : (r - 1.0f);
            unsigned u = __float_as_uint(p);
            u = (u & 0x80000000u) ? ~u : (u | 0x80000000u);   // order-preserving
            bool v = (mbits >> k) & 1u;
            key[k] = v ? ((u & 0xFFFFFFE0u) | (unsigned)k)
                       : (0xFFFFFFE0u | (unsigned)k);          // invalid -> max
        }

        // ---- Batcher odd-even mergesort, n = 24 (fully unrolled network) ----
        {
            const int n = 24;
            #pragma unroll
            for (int p = 1; p < n; p *= 2) {
                #pragma unroll
                for (int k = p; k >= 1; k /= 2) {
                    #pragma unroll
                    for (int j = k % p; j <= n - 1 - k; j += 2 * k) {
                        #pragma unroll
                        for (int i = 0; i < k; i++) {
                            if (i <= n - j - k - 1) {
                                if ((i + j) / (2 * p) == (i + j + k) / (2 * p)) {
                                    ce(key[i + j], key[i + j + k]);
                                }
                            }
                        }
                    }
                }
            }
        }

        // ---- shoelace over sorted valid points (gather via low 5 bits) ----
        int   o0  = (int)(key[0] & 31u);
        float s0x = px_sh[o0][tid], s0y = py_sh[o0][tid];
        float prevx = s0x, prevy = s0y;
        float s = 0.0f;
        #pragma unroll
        for (int i = 1; i < 24; i++) {
            int o = (int)(key[i] & 31u);
            bool v = i < cnt;
            float qx = v ? px_sh[o][tid] : s0x;
            float qy = v ? py_sh[o][tid] : s0y;
            s += prevx * qy - qx * prevy;
            prevx = qx;
            prevy = qy;
        }
        s += prevx * s0y - s0x * prevy;
        float inter = 0.5f * fabsf(s);
        if (cnt < 3) inter = 0.0f;

        float iou = inter / (a1 + a2 - inter + EPS_DEN);
        loss = 1.0f - iou;
    }

    // ---- block reduction ----
    #pragma unroll
    for (int off = 16; off > 0; off >>= 1)
        loss += __shfl_down_sync(0xffffffff, loss, off);
    int lane = tid & 31;
    int wid  = tid >> 5;
    if (lane == 0) sdata[wid] = loss;
    __syncthreads();
    if (wid == 0) {
        loss = (lane < TPB / 32) ? sdata[lane] : 0.0f;
        #pragma unroll
        for (int off = 16; off > 0; off >>= 1)
            loss += __shfl_down_sync(0xffffffff, loss, off);
        if (lane == 0) atomicAdd(out, loss / (float)total);
    }
}

extern "C" void kernel_launch(void* const* d_in, const int* in_sizes, int n_in,
                              void* d_out, int out_size)
{
    const float4* gt    = (const float4*)d_in[0];
    const float4* det   = (const float4*)d_in[1];
    const int*    sizes = (const int*)d_in[2];
    float*        out   = (float*)d_out;

    int B = in_sizes[2] / 2;
    int N = in_sizes[0] / (8 * B);
    int total = B * N;

    iou_zero_kernel<<<1, 32>>>(out);
    int blocks = (total + TPB - 1) / TPB;
    iou_loss_kernel<<<blocks, TPB>>>(gt, det, sizes, out, B, N);
}

// round 6
// speedup vs baseline: 7.2741x; 1.4145x over previous
#include <cuda_runtime.h>

#define EPS_DEN 1e-9f
#define EPS_IN  1e-6f
#define TPB 128
#define NS 16   // compacted slots / sort width

__global__ void iou_zero_kernel(float* out) {
    if (threadIdx.x == 0 && blockIdx.x == 0) out[0] = 0.0f;
}

__device__ __forceinline__ void ce(unsigned &a, unsigned &b) {
    unsigned lo = min(a, b);
    unsigned hi = max(a, b);
    a = lo; b = hi;
}

__global__ __launch_bounds__(TPB)
void iou_loss_kernel(const float4* __restrict__ gt,
                     const float4* __restrict__ det,
                     const int*   __restrict__ sizes,
                     float* __restrict__ out,
                     int B, int N)
{
    // [slot][tid] layout: bank = tid%32 for any slot -> conflict-free
    __shared__ float px_sh[NS][TPB];
    __shared__ float py_sh[NS][TPB];
    __shared__ float sdata[TPB / 32];

    int tid   = threadIdx.x;
    int idx   = blockIdx.x * TPB + tid;
    int total = B * N;
    float loss = 0.0f;

    if (idx < total) {
        int b = idx / N;
        float sx = (float)sizes[2 * b + 1];
        float sy = (float)sizes[2 * b + 0];

        float4 g0 = gt[2 * idx],  g1 = gt[2 * idx + 1];
        float4 d0 = det[2 * idx], d1 = det[2 * idx + 1];

        float p1x[4], p1y[4], p2x[4], p2y[4];
        p1x[0] = g0.x * sx; p1y[0] = g0.y * sy;
        p1x[1] = g0.z * sx; p1y[1] = g0.w * sy;
        p1x[2] = g1.x * sx; p1y[2] = g1.y * sy;
        p1x[3] = g1.z * sx; p1y[3] = g1.w * sy;
        p2x[0] = d0.x; p2y[0] = d0.y;
        p2x[1] = d0.z; p2y[1] = d0.w;
        p2x[2] = d1.x; p2y[2] = d1.y;
        p2x[3] = d1.z; p2y[3] = d1.w;

        int   cnt = 0;          // compacted write cursor == popc so far
        float cx = 0.0f, cy = 0.0f;

        // ---- 16 edge-pair intersections -> compacted smem slots ----
        #pragma unroll
        for (int i = 0; i < 4; i++) {
            int i1 = (i + 1) & 3;
            float a0x = p1x[i], a0y = p1y[i];
            float d1x = p1x[i1] - a0x, d1y = p1y[i1] - a0y;
            #pragma unroll
            for (int j = 0; j < 4; j++) {
                int j1 = (j + 1) & 3;
                float b0x = p2x[j], b0y = p2y[j];
                float d2x = p2x[j1] - b0x, d2y = p2y[j1] - b0y;
                float rx = b0x - a0x, ry = b0y - a0y;
                float den = d1x * d2y - d1y * d2x;
                bool  dok = fabsf(den) > EPS_DEN;
                float invd = 1.0f / (dok ? den : 1.0f);
                float t = (rx * d2y - ry * d2x) * invd;
                float u = (rx * d1y - ry * d1x) * invd;
                bool v = dok && (t >= 0.0f) && (t <= 1.0f)
                             && (u >= 0.0f) && (u <= 1.0f);
                if (v) {
                    float X = a0x + t * d1x;
                    float Y = a0y + t * d1y;
                    if (cnt < NS) { px_sh[cnt][tid] = X; py_sh[cnt][tid] = Y; }
                    cnt++; cx += X; cy += Y;
                }
            }
        }

        // ---- p1 vertices inside p2 ----
        #pragma unroll
        for (int q = 0; q < 4; q++) {
            bool allpos = true, allneg = true;
            #pragma unroll
            for (int e = 0; e < 4; e++) {
                int e1 = (e + 1) & 3;
                float ex = p2x[e1] - p2x[e], ey = p2y[e1] - p2y[e];
                float dx = p1x[q] - p2x[e], dy = p1y[q] - p2y[e];
                float cr = ex * dy - ey * dx;
                allpos = allpos && (cr >= -EPS_IN);
                allneg = allneg && (cr <=  EPS_IN);
            }
            if (allpos || allneg) {
                if (cnt < NS) { px_sh[cnt][tid] = p1x[q]; py_sh[cnt][tid] = p1y[q]; }
                cnt++; cx += p1x[q]; cy += p1y[q];
            }
        }

        // ---- p2 vertices inside p1 ----
        #pragma unroll
        for (int q = 0; q < 4; q++) {
            bool allpos = true, allneg = true;
            #pragma unroll
            for (int e = 0; e < 4; e++) {
                int e1 = (e + 1) & 3;
                float ex = p1x[e1] - p1x[e], ey = p1y[e1] - p1y[e];
                float dx = p2x[q] - p1x[e], dy = p2y[q] - p1y[e];
                float cr = ex * dy - ey * dx;
                allpos = allpos && (cr >= -EPS_IN);
                allneg = allneg && (cr <=  EPS_IN);
            }
            if (allpos || allneg) {
                if (cnt < NS) { px_sh[cnt][tid] = p2x[q]; py_sh[cnt][tid] = p2y[q]; }
                cnt++; cx += p2x[q]; cy += p2y[q];
            }
        }

        // ---- quad areas ----
        float a1 = 0.0f, a2 = 0.0f;
        #pragma unroll
        for (int k = 0; k < 4; k++) {
            int k1 = (k + 1) & 3;
            a1 += p1x[k] * p1y[k1] - p1x[k1] * p1y[k];
            a2 += p2x[k] * p2y[k1] - p2x[k1] * p2y[k];
        }
        a1 = 0.5f * fabsf(a1);
        a2 = 0.5f * fabsf(a2);

        // ---- centroid ----
        float inv = 1.0f / (float)(cnt > 1 ? cnt : 1);
        cx *= inv;
        cy *= inv;
        int cslot = min(cnt, NS);   // slots actually stored

        // ---- keys: pseudo-angle (order-preserving uint), compacted index low 4 bits ----
        unsigned key[NS];
        #pragma unroll
        for (int k = 0; k < NS; k++) {
            float x = px_sh[k][tid], y = py_sh[k][tid];
            float dx = x - cx, dy = y - cy;
            float r = __fdividef(dx, fabsf(dx) + fabsf(dy) + 1e-30f);
            float p = (dy >= 0.0f) ? (1.0f - r) : (r - 1.0f);
            unsigned u = __float_as_uint(p);
            u = (u & 0x80000000u) ? ~u : (u | 0x80000000u);
            bool v = k < cslot;
            key[k] = v ? ((u & 0xFFFFFFF0u) | (unsigned)k)
                       : (0xFFFFFFF0u | (unsigned)k);
        }

        // ---- Batcher odd-even mergesort, n = 16 (63 compare-exchanges) ----
        {
            const int n = NS;
            #pragma unroll
            for (int p = 1; p < n; p *= 2) {
                #pragma unroll
                for (int k = p; k >= 1; k /= 2) {
                    #pragma unroll
                    for (int j = k % p; j <= n - 1 - k; j += 2 * k) {
                        #pragma unroll
                        for (int i = 0; i < k; i++) {
                            if (i <= n - j - k - 1) {
                                if ((i + j) / (2 * p) == (i + j + k) / (2 * p)) {
                                    ce(key[i + j], key[i + j + k]);
                                }
                            }
                        }
                    }
                }
            }
        }

        // ---- shoelace over sorted valid points ----
        int   o0  = (int)(key[0] & 15u);
        float s0x = px_sh[o0][tid], s0y = py_sh[o0][tid];
        float prevx = s0x, prevy = s0y;
        float s = 0.0f;
        #pragma unroll
        for (int i = 1; i < NS; i++) {
            int o = (int)(key[i] & 15u);
            bool v = i < cslot;
            float qx = v ? px_sh[o][tid] : s0x;
            float qy = v ? py_sh[o][tid] : s0y;
            s += prevx * qy - qx * prevy;
            prevx = qx;
            prevy = qy;
        }
        s += prevx * s0y - s0x * prevy;
        float inter = 0.5f * fabsf(s);
        if (cnt < 3) inter = 0.0f;

        float iou = inter / (a1 + a2 - inter + EPS_DEN);
        loss = 1.0f - iou;
    }

    // ---- block reduction ----
    #pragma unroll
    for (int off = 16; off > 0; off >>= 1)
        loss += __shfl_down_sync(0xffffffff, loss, off);
    int lane = tid & 31;
    int wid  = tid >> 5;
    if (lane == 0) sdata[wid] = loss;
    __syncthreads();
    if (wid == 0) {
        loss = (lane < TPB / 32) ? sdata[lane] : 0.0f;
        #pragma unroll
        for (int off = 16; off > 0; off >>= 1)
            loss += __shfl_down_sync(0xffffffff, loss, off);
        if (lane == 0) atomicAdd(out, loss / (float)total);
    }
}

extern "C" void kernel_launch(void* const* d_in, const int* in_sizes, int n_in,
                              void* d_out, int out_size)
{
    const float4* gt    = (const float4*)d_in[0];
    const float4* det   = (const float4*)d_in[1];
    const int*    sizes = (const int*)d_in[2];
    float*        out   = (float*)d_out;

    int B = in_sizes[2] / 2;
    int N = in_sizes[0] / (8 * B);
    int total = B * N;

    iou_zero_kernel<<<1, 32>>>(out);
    int blocks = (total + TPB - 1) / TPB;
    iou_loss_kernel<<<blocks, TPB>>>(gt, det, sizes, out, B, N);
}

// round 7
// speedup vs baseline: 8.4617x; 1.1633x over previous
#include <cuda_runtime.h>

#define EPS_DEN 1e-9f
#define EPS_IN  1e-6f
#define TPB 128
#define NS 8    // compacted slots / sort width (convex-quad intersection has <= 8 vertices)

__global__ void iou_zero_kernel(float* out) {
    if (threadIdx.x == 0 && blockIdx.x == 0) out[0] = 0.0f;
}

__device__ __forceinline__ void ce(unsigned &a, unsigned &b) {
    unsigned lo = min(a, b);
    unsigned hi = max(a, b);
    a = lo; b = hi;
}

__global__ __launch_bounds__(TPB)
void iou_loss_kernel(const float4* __restrict__ gt,
                     const float4* __restrict__ det,
                     const int*   __restrict__ sizes,
                     float* __restrict__ out,
                     int B, int N)
{
    // [slot][tid] layout: bank = tid%32 for any slot -> conflict-free
    __shared__ float px_sh[NS][TPB];
    __shared__ float py_sh[NS][TPB];
    __shared__ float sdata[TPB / 32];

    int tid   = threadIdx.x;
    int idx   = blockIdx.x * TPB + tid;
    int total = B * N;
    float loss = 0.0f;

    if (idx < total) {
        int b = idx / N;
        float sx = (float)sizes[2 * b + 1];
        float sy = (float)sizes[2 * b + 0];

        float4 g0 = gt[2 * idx],  g1 = gt[2 * idx + 1];
        float4 d0 = det[2 * idx], d1 = det[2 * idx + 1];

        float p1x[4], p1y[4], p2x[4], p2y[4];
        p1x[0] = g0.x * sx; p1y[0] = g0.y * sy;
        p1x[1] = g0.z * sx; p1y[1] = g0.w * sy;
        p1x[2] = g1.x * sx; p1y[2] = g1.y * sy;
        p1x[3] = g1.z * sx; p1y[3] = g1.w * sy;
        p2x[0] = d0.x; p2y[0] = d0.y;
        p2x[1] = d0.z; p2y[1] = d0.w;
        p2x[2] = d1.x; p2y[2] = d1.y;
        p2x[3] = d1.z; p2y[3] = d1.w;

        // edge vectors (hoisted once)
        float e1x[4], e1y[4], e2x[4], e2y[4];
        #pragma unroll
        for (int k = 0; k < 4; k++) {
            int k1 = (k + 1) & 3;
            e1x[k] = p1x[k1] - p1x[k]; e1y[k] = p1y[k1] - p1y[k];
            e2x[k] = p2x[k1] - p2x[k]; e2y[k] = p2y[k1] - p2y[k];
        }

        int   cnt = 0;
        float cx = 0.0f, cy = 0.0f;

        // ---- 16 edge-pair intersections -> compacted smem slots ----
        #pragma unroll
        for (int i = 0; i < 4; i++) {
            float a0x = p1x[i], a0y = p1y[i];
            float d1x = e1x[i], d1y = e1y[i];
            #pragma unroll
            for (int j = 0; j < 4; j++) {
                float b0x = p2x[j], b0y = p2y[j];
                float d2x = e2x[j], d2y = e2y[j];
                float rx = b0x - a0x, ry = b0y - a0y;
                float den = d1x * d2y - d1y * d2x;
                bool  dok = fabsf(den) > EPS_DEN;
                float invd = 1.0f / (dok ? den : 1.0f);
                float t = (rx * d2y - ry * d2x) * invd;
                float u = (rx * d1y - ry * d1x) * invd;
                bool v = dok && (t >= 0.0f) && (t <= 1.0f)
                             && (u >= 0.0f) && (u <= 1.0f);
                if (v) {
                    float X = a0x + t * d1x;
                    float Y = a0y + t * d1y;
                    if (cnt < NS) { px_sh[cnt][tid] = X; py_sh[cnt][tid] = Y; }
                    cnt++; cx += X; cy += Y;
                }
            }
        }

        // ---- p1 vertices inside p2 ----
        #pragma unroll
        for (int q = 0; q < 4; q++) {
            bool allpos = true, allneg = true;
            #pragma unroll
            for (int e = 0; e < 4; e++) {
                float dx = p1x[q] - p2x[e], dy = p1y[q] - p2y[e];
                float cr = e2x[e] * dy - e2y[e] * dx;
                allpos = allpos && (cr >= -EPS_IN);
                allneg = allneg && (cr <=  EPS_IN);
            }
            if (allpos || allneg) {
                if (cnt < NS) { px_sh[cnt][tid] = p1x[q]; py_sh[cnt][tid] = p1y[q]; }
                cnt++; cx += p1x[q]; cy += p1y[q];
            }
        }

        // ---- p2 vertices inside p1 ----
        #pragma unroll
        for (int q = 0; q < 4; q++) {
            bool allpos = true, allneg = true;
            #pragma unroll
            for (int e = 0; e < 4; e++) {
                float dx = p2x[q] - p1x[e], dy = p2y[q] - p1y[e];
                float cr = e1x[e] * dy - e1y[e] * dx;
                allpos = allpos && (cr >= -EPS_IN);
                allneg = allneg && (cr <=  EPS_IN);
            }
            if (allpos || allneg) {
                if (cnt < NS) { px_sh[cnt][tid] = p2x[q]; py_sh[cnt][tid] = p2y[q]; }
                cnt++; cx += p2x[q]; cy += p2y[q];
            }
        }

        // ---- quad areas ----
        float a1 = 0.0f, a2 = 0.0f;
        #pragma unroll
        for (int k = 0; k < 4; k++) {
            int k1 = (k + 1) & 3;
            a1 += p1x[k] * p1y[k1] - p1x[k1] * p1y[k];
            a2 += p2x[k] * p2y[k1] - p2x[k1] * p2y[k];
        }
        a1 = 0.5f * fabsf(a1);
        a2 = 0.5f * fabsf(a2);

        // ---- centroid ----
        float inv = 1.0f / (float)(cnt > 1 ? cnt : 1);
        cx *= inv;
        cy *= inv;
        int cslot = min(cnt, NS);

        // ---- keys: pseudo-angle (order-preserving uint), compacted index low 3 bits ----
        unsigned key[NS];
        #pragma unroll
        for (int k = 0; k < NS; k++) {
            float x = px_sh[k][tid], y = py_sh[k][tid];
            float dx = x - cx, dy = y - cy;
            float r = __fdividef(dx, fabsf(dx) + fabsf(dy) + 1e-30f);
            float p = (dy >= 0.0f) ? (1.0f - r) : (r - 1.0f);
            unsigned u = __float_as_uint(p);
            u = (u & 0x80000000u) ? ~u : (u | 0x80000000u);
            bool v = k < cslot;
            key[k] = v ? ((u & 0xFFFFFFF8u) | (unsigned)k)
                       : (0xFFFFFFF8u | (unsigned)k);
        }

        // ---- Batcher odd-even mergesort, n = 8 (19 compare-exchanges) ----
        {
            const int n = NS;
            #pragma unroll
            for (int p = 1; p < n; p *= 2) {
                #pragma unroll
                for (int k = p; k >= 1; k /= 2) {
                    #pragma unroll
                    for (int j = k % p; j <= n - 1 - k; j += 2 * k) {
                        #pragma unroll
                        for (int i = 0; i < k; i++) {
                            if (i <= n - j - k - 1) {
                                if ((i + j) / (2 * p) == (i + j + k) / (2 * p)) {
                                    ce(key[i + j], key[i + j + k]);
                                }
                            }
                        }
                    }
                }
            }
        }

        // ---- shoelace over sorted valid points ----
        int   o0  = (int)(key[0] & 7u);
        float s0x = px_sh[o0][tid], s0y = py_sh[o0][tid];
        float prevx = s0x, prevy = s0y;
        float s = 0.0f;
        #pragma unroll
        for (int i = 1; i < NS; i++) {
            int o = (int)(key[i] & 7u);
            bool v = i < cslot;
            float qx = v ? px_sh[o][tid] : s0x;
            float qy = v ? py_sh[o][tid] : s0y;
            s += prevx * qy - qx * prevy;
            prevx = qx;
            prevy = qy;
        }
        s += prevx * s0y - s0x * prevy;
        float inter = 0.5f * fabsf(s);
        if (cnt < 3) inter = 0.0f;

        float iou = inter / (a1 + a2 - inter + EPS_DEN);
        loss = 1.0f - iou;
    }

    // ---- block reduction ----
    #pragma unroll
    for (int off = 16; off > 0; off >>= 1)
        loss += __shfl_down_sync(0xffffffff, loss, off);
    int lane = tid & 31;
    int wid  = tid >> 5;
    if (lane == 0) sdata[wid] = loss;
    __syncthreads();
    if (wid == 0) {
        loss = (lane < TPB / 32) ? sdata[lane] : 0.0f;
        #pragma unroll
        for (int off = 16; off > 0; off >>= 1)
            loss += __shfl_down_sync(0xffffffff, loss, off);
        if (lane == 0) atomicAdd(out, loss / (float)total);
    }
}

extern "C" void kernel_launch(void* const* d_in, const int* in_sizes, int n_in,
                              void* d_out, int out_size)
{
    const float4* gt    = (const float4*)d_in[0];
    const float4* det   = (const float4*)d_in[1];
    const int*    sizes = (const int*)d_in[2];
    float*        out   = (float*)d_out;

    int B = in_sizes[2] / 2;
    int N = in_sizes[0] / (8 * B);
    int total = B * N;

    iou_zero_kernel<<<1, 32>>>(out);
    int blocks = (total + TPB - 1) / TPB;
    iou_loss_kernel<<<blocks, TPB>>>(gt, det, sizes, out, B, N);
}